// round 9
// baseline (speedup 1.0000x reference)
#include <cuda_runtime.h>
#include <math.h>

// ---------------- scratch (device globals; no allocation) ----------------
__device__ float g_h0[1024];
__device__ float g_h1[1024];
__device__ float g_h2[1024];
__device__ float g_acc_qkv[5120];        // [q:8*hd][k:hd][v:hd]
__device__ float g_scores[8 * 2048];     // [h][j] -> probs after k_probs
__device__ __align__(16) float g_attn_part[32 * 4096]; // [row][h*hd+d]
__device__ float g_acc_o[1024];
__device__ float g_acc_gu[8192];         // [g:4096][u:4096]
__device__ float g_acc_mlp[1024];
__device__ float g_acc_pg[256];
__device__ float g_acc_pli[1024];
__device__ __align__(16) float g_kcur[15][512];
__device__ __align__(16) float g_vcur[15][512];

// ---------------- helpers ----------------
template <int NW>
__device__ __forceinline__ float bsum(float v, float* sred) {
    int tid = threadIdx.x;
    #pragma unroll
    for (int o = 16; o; o >>= 1) v += __shfl_xor_sync(0xffffffff, v, o);
    if ((tid & 31) == 0) sred[tid >> 5] = v;
    __syncthreads();
    if (tid == 0) {
        float t = sred[0];
        #pragma unroll
        for (int i = 1; i < NW; i++) t += sred[i];
        sred[0] = t;
    }
    __syncthreads();
    float r = sred[0];
    __syncthreads();
    return r;
}

template <int NW>
__device__ __forceinline__ float bmax(float v, float* sred) {
    int tid = threadIdx.x;
    #pragma unroll
    for (int o = 16; o; o >>= 1) v = fmaxf(v, __shfl_xor_sync(0xffffffff, v, o));
    if ((tid & 31) == 0) sred[tid >> 5] = v;
    __syncthreads();
    if (tid == 0) {
        float t = sred[0];
        #pragma unroll
        for (int i = 1; i < NW; i++) t = fmaxf(t, sred[i]);
        sred[0] = t;
    }
    __syncthreads();
    float r = sred[0];
    __syncthreads();
    return r;
}

__device__ __forceinline__ float gelu_tanh(float x) {
    float x3 = x * x * x;
    return 0.5f * x * (1.f + tanhf(0.7978845608028654f * (x + 0.044715f * x3)));
}

__device__ __forceinline__ void fma4(float4& a, float x, const float4 w) {
    a.x += x * w.x; a.y += x * w.y; a.z += x * w.z; a.w += x * w.w;
}

// ---------------- embed ----------------
__global__ __launch_bounds__(256) void k_embed(const float* __restrict__ embed,
                                               const float* __restrict__ img,
                                               const int* __restrict__ ids) {
    __shared__ float sred[8];
    int tid = threadIdx.x;
    int id = ids[0];
    float iv[4];
    float sa = 0.f;
    #pragma unroll
    for (int i = 0; i < 4; i++) { iv[i] = img[tid + i * 256]; sa += fabsf(iv[i]); }
    sa = bsum<8>(sa, sred);
    bool isimg = sa > 0.f;
    const float* er = embed + (size_t)id * 1024;
    #pragma unroll
    for (int i = 0; i < 4; i++) {
        int idx = tid + i * 256;
        g_h0[idx] = isimg ? iv[i] : er[idx] * 32.0f; // sqrt(1024)=32
    }
    for (int z = tid; z < 5120; z += 256) g_acc_qkv[z] = 0.f;
}

// ---------------- K1: QKV gemv (+ finish previous layer's h) ----------------
__global__ __launch_bounds__(128) void k_qkv(const float* __restrict__ Wq,
                                             const float* __restrict__ Wk,
                                             const float* __restrict__ Wv,
                                             const float* __restrict__ ln_in,
                                             const float* __restrict__ ln_ppli,
                                             const float* __restrict__ lscal,
                                             int l, int hd) {
    __shared__ __align__(16) float xs[1024];
    __shared__ float sred[8];
    int tid = threadIdx.x;
    float h0v[8];
    if (l == 0) {
        #pragma unroll
        for (int i = 0; i < 8; i++) h0v[i] = g_h0[tid + i * 128];
    } else {
        const float* lw = ln_ppli + (size_t)(l - 1) * 1024;
        float pv[8]; float ss = 0.f;
        #pragma unroll
        for (int i = 0; i < 8; i++) { pv[i] = g_acc_pli[tid + i * 128]; ss += pv[i] * pv[i]; }
        ss = bsum<4>(ss, sred);
        float r = rsqrtf(ss / 1024.f + 1e-6f);
        float sc = lscal[l - 1];
        #pragma unroll
        for (int i = 0; i < 8; i++) {
            int idx = tid + i * 128;
            h0v[i] = (g_h2[idx] + pv[i] * r * (1.f + lw[idx])) * sc;
        }
        if (blockIdx.x == 0 && blockIdx.y == 0)
            #pragma unroll
            for (int i = 0; i < 8; i++) g_h0[tid + i * 128] = h0v[i];
    }
    {
        float ss = 0.f;
        #pragma unroll
        for (int i = 0; i < 8; i++) ss += h0v[i] * h0v[i];
        ss = bsum<4>(ss, sred);
        float r = rsqrtf(ss / 1024.f + 1e-6f);
        const float* lw = ln_in + (size_t)l * 1024;
        #pragma unroll
        for (int i = 0; i < 8; i++) { int idx = tid + i * 128; xs[idx] = h0v[i] * r * (1.f + lw[idx]); }
    }
    __syncthreads();

    int o = (blockIdx.x * 128 + tid) * 4;
    int qsize = 8 * hd;
    int lhd = (hd == 512) ? 9 : 8;
    const float* wbase; int stride;
    if (o < qsize) {
        int hh = o >> lhd; int d = o & (hd - 1);
        wbase = Wq + (size_t)l * 4194304 + hh * 512 + d; stride = 4096;
    } else if (o < qsize + hd) {
        wbase = Wk + (size_t)l * 524288 + (o - qsize); stride = 512;
    } else {
        wbase = Wv + (size_t)l * 524288 + (o - qsize - hd); stride = 512;
    }
    int e0 = blockIdx.y * 64;
    const float* wp = wbase + (size_t)e0 * stride;
    float4 acc = {0.f, 0.f, 0.f, 0.f};
    #pragma unroll 16
    for (int e = 0; e < 64; e++) {
        float4 w = *(const float4*)wp;
        fma4(acc, xs[e0 + e], w);
        wp += stride;
    }
    atomicAdd(&g_acc_qkv[o + 0], acc.x);
    atomicAdd(&g_acc_qkv[o + 1], acc.y);
    atomicAdd(&g_acc_qkv[o + 2], acc.z);
    atomicAdd(&g_acc_qkv[o + 3], acc.w);
}

// ---------------- K2: finalize q/k/v (rms+rope) + scores ----------------
__global__ __launch_bounds__(256) void k_scores(const float* __restrict__ kv,
                                                const float* __restrict__ qn_w,
                                                const float* __restrict__ kn_w,
                                                const float* __restrict__ cost,
                                                const float* __restrict__ sint,
                                                const int* __restrict__ pos_ids,
                                                int l, int hd) {
    __shared__ __align__(16) float qf[8 * 512];
    __shared__ __align__(16) float kc[512];
    __shared__ __align__(16) float vc[512];
    __shared__ float sred[8];
    int tid = threadIdx.x, wid = tid >> 5, lane = tid & 31;
    int pos = pos_ids[0];
    int half = hd >> 1;
    int lhd = (hd == 512) ? 9 : 8;
    const float* cr = cost + (size_t)pos * hd;
    const float* sr = sint + (size_t)pos * hd;

    // zero acc_o for K5's atomics
    { int gt = blockIdx.x * 256 + tid; if (gt < 1024) g_acc_o[gt] = 0.f; }

    // q rms per head (warp wid -> head wid)
    {
        const float* qraw = g_acc_qkv + (size_t)wid * hd;
        float ss = 0.f;
        for (int i = lane; i < hd; i += 32) { float v = qraw[i]; ss += v * v; }
        #pragma unroll
        for (int o = 16; o; o >>= 1) ss += __shfl_xor_sync(0xffffffff, ss, o);
        float r = rsqrtf(ss / (float)hd + 1e-6f);
        const float* qw = qn_w + (size_t)l * 512;
        for (int i = lane; i < hd; i += 32) qf[wid * hd + i] = qraw[i] * r * (1.f + qw[i]);
    }
    // k rms
    {
        float ss = 0.f;
        for (int i = tid; i < hd; i += 256) { float v = g_acc_qkv[8 * hd + i]; ss += v * v; }
        ss = bsum<8>(ss, sred);
        float r = rsqrtf(ss / (float)hd + 1e-6f);
        const float* kw = kn_w + (size_t)l * 512;
        for (int i = tid; i < hd; i += 256) kc[i] = g_acc_qkv[8 * hd + i] * r * (1.f + kw[i]);
    }
    // v norm
    {
        float ss = 0.f;
        for (int i = tid; i < hd; i += 256) { float v = g_acc_qkv[9 * hd + i]; ss += v * v; }
        ss = bsum<8>(ss, sred);
        float r = rsqrtf(ss / (float)hd + 1e-6f);
        for (int i = tid; i < hd; i += 256) vc[i] = g_acc_qkv[9 * hd + i] * r;
    }
    __syncthreads();
    // rope q,k (read pairs to regs, sync, write)
    float tq[16]; float tk[2];
    int nq = (8 * hd) / 256;  // 8 or 16
    int nk = hd / 256;        // 1 or 2
    for (int i = 0; i < nq; i++) {
        int idx = tid + i * 256;
        int h = idx >> lhd; int d = idx & (hd - 1);
        float x = qf[idx];
        float rot = (d < half) ? -qf[h * hd + d + half] : qf[h * hd + d - half];
        tq[i] = x * cr[d] + rot * sr[d];
    }
    for (int i = 0; i < nk; i++) {
        int d = tid + i * 256;
        float x = kc[d];
        float rot = (d < half) ? -kc[d + half] : kc[d - half];
        tk[i] = x * cr[d] + rot * sr[d];
    }
    __syncthreads();
    for (int i = 0; i < nq; i++) qf[tid + i * 256] = tq[i];
    for (int i = 0; i < nk; i++) kc[tid + i * 256] = tk[i];
    __syncthreads();
    if (blockIdx.x == 0) {
        for (int i = 0; i < nk; i++) {
            g_kcur[l][tid + i * 256] = kc[tid + i * 256];
            g_vcur[l][tid + i * 256] = vc[tid + i * 256];
        }
    }
    // scores: warp wid handles j = blockIdx.x*8 + wid, stride gridDim.x*8
    int it = hd >> 7; // float4 iterations per lane: 2 or 4
    for (int j = blockIdx.x * 8 + wid; j <= pos; j += gridDim.x * 8) {
        const float4* Kr = (j == pos) ? (const float4*)kc
                                      : (const float4*)(kv + ((size_t)l * 2048 + j) * 512);
        float a[8] = {0, 0, 0, 0, 0, 0, 0, 0};
        #pragma unroll
        for (int t = 0; t < 4; t++) {
            if (t < it) {
                int i4 = lane + t * 32;
                float4 kvv = Kr[i4];
                #pragma unroll
                for (int h = 0; h < 8; h++) {
                    float4 q = *(const float4*)&qf[h * hd + i4 * 4];
                    a[h] += q.x * kvv.x + q.y * kvv.y + q.z * kvv.z + q.w * kvv.w;
                }
            }
        }
        #pragma unroll
        for (int h = 0; h < 8; h++) {
            float t = a[h];
            #pragma unroll
            for (int o = 16; o; o >>= 1) t += __shfl_xor_sync(0xffffffff, t, o);
            if (lane == 0) g_scores[h * 2048 + j] = t;
        }
    }
}

// ---------------- K3: softmax normalize per head (in place) ----------------
__global__ __launch_bounds__(256) void k_probs(const int* __restrict__ pos_ids) {
    __shared__ float sred[8];
    int tid = threadIdx.x;
    int h = blockIdx.x;
    int pos = pos_ids[0];
    float* sc = g_scores + (size_t)h * 2048;
    float mx = -1e30f;
    for (int j = tid; j <= pos; j += 256) mx = fmaxf(mx, sc[j]);
    mx = bmax<8>(mx, sred);
    float se = 0.f;
    for (int j = tid; j <= pos; j += 256) se += __expf(sc[j] - mx);
    se = bsum<8>(se, sred);
    float inv = 1.f / se;
    for (int j = tid; j <= pos; j += 256) sc[j] = __expf(sc[j] - mx) * inv;
    // zero acc_gu for k_ff1
    for (int z = h * 256 + tid; z < 8192; z += 2048) g_acc_gu[z] = 0.f;
}

// ---------------- K4: weighted V, all heads per block (j-chunk partials) ----------------
__global__ __launch_bounds__(256) void k_attnv(const float* __restrict__ kv,
                                               const int* __restrict__ pos_ids,
                                               int l, int hd) {
    int tid = threadIdx.x;
    int pos = pos_ids[0];
    int d4c = hd >> 2;              // 64 or 128
    int d4 = tid & (d4c - 1);
    int sub = (hd == 512) ? (tid >> 7) : (tid >> 6);
    int S = 256 / d4c;              // 2 or 4
    int j0 = blockIdx.x * 256;
    float4 a[8];
    #pragma unroll
    for (int h = 0; h < 8; h++) a[h] = make_float4(0.f, 0.f, 0.f, 0.f);

    const float4* Vb = (const float4*)(kv + (size_t)(15 + l) * 2048 * 512);
    int jmax = (pos < j0 + 255) ? pos : (j0 + 255);
    for (int j = j0 + sub; j <= jmax; j += S) {
        const float4* vr = (j == pos) ? (const float4*)g_vcur[l] : (Vb + (size_t)j * 128);
        float4 v = vr[d4];
        #pragma unroll
        for (int h = 0; h < 8; h++) {
            float p = g_scores[h * 2048 + j];
            fma4(a[h], p, v);
        }
    }
    // write partial row = chunk*S + sub (zeros if no j in range)
    float* op = g_attn_part + (size_t)(blockIdx.x * S + sub) * 4096;
    #pragma unroll
    for (int h = 0; h < 8; h++)
        *(float4*)&op[h * hd + d4 * 4] = a[h];
}

// ---------------- K5: Wo gemv ----------------
template <int NROWS>
__global__ __launch_bounds__(256) void k_wo(const float* __restrict__ Wo, int l, int hd) {
    __shared__ float xs[64];
    int tid = threadIdx.x;
    int i0 = blockIdx.y * 64;
    if (tid < 64) {
        float s = 0.f;
        #pragma unroll
        for (int c = 0; c < NROWS; c++) s += g_attn_part[(size_t)c * 4096 + i0 + tid];
        xs[tid] = s;
    }
    __syncthreads();
    int lhd = (hd == 512) ? 9 : 8;
    int row0 = (i0 >> lhd) * 512 + (i0 & (hd - 1));
    const float* wp = Wo + (size_t)l * 4194304 + (size_t)row0 * 1024 + tid * 4;
    float4 acc = {0.f, 0.f, 0.f, 0.f};
    #pragma unroll 16
    for (int i = 0; i < 64; i++) {
        float4 w = *(const float4*)wp;
        fma4(acc, xs[i], w);
        wp += 1024;
    }
    int o = tid * 4;
    atomicAdd(&g_acc_o[o + 0], acc.x);
    atomicAdd(&g_acc_o[o + 1], acc.y);
    atomicAdd(&g_acc_o[o + 2], acc.z);
    atomicAdd(&g_acc_o[o + 3], acc.w);
    int gt = blockIdx.y * 256 + tid;
    if (gt < 1024) g_acc_mlp[gt] = 0.f;
}

// ---------------- K6: FF gate+up gemv ----------------
__global__ __launch_bounds__(256) void k_ff1(const float* __restrict__ Wg,
                                             const float* __restrict__ Wu,
                                             const float* __restrict__ ln_pa,
                                             const float* __restrict__ ln_pff, int l) {
    __shared__ __align__(16) float xs[1024];
    __shared__ float sred[8];
    int tid = threadIdx.x;
    float ov[4], h1v[4];
    float ss = 0.f;
    #pragma unroll
    for (int i = 0; i < 4; i++) { ov[i] = g_acc_o[tid + i * 256]; ss += ov[i] * ov[i]; }
    ss = bsum<8>(ss, sred);
    float r = rsqrtf(ss / 1024.f + 1e-6f);
    const float* wpa = ln_pa + (size_t)l * 1024;
    #pragma unroll
    for (int i = 0; i < 4; i++) { int idx = tid + i * 256; h1v[i] = g_h0[idx] + ov[i] * r * (1.f + wpa[idx]); }
    if (blockIdx.x == 0 && blockIdx.y == 0)
        #pragma unroll
        for (int i = 0; i < 4; i++) g_h1[tid + i * 256] = h1v[i];
    float s2 = 0.f;
    #pragma unroll
    for (int i = 0; i < 4; i++) s2 += h1v[i] * h1v[i];
    s2 = bsum<8>(s2, sred);
    float r2 = rsqrtf(s2 / 1024.f + 1e-6f);
    const float* wpf = ln_pff + (size_t)l * 1024;
    #pragma unroll
    for (int i = 0; i < 4; i++) { int idx = tid + i * 256; xs[idx] = h1v[i] * r2 * (1.f + wpf[idx]); }
    __syncthreads();

    int o = (blockIdx.x * 256 + tid) * 4;  // 0..8191
    const float* wb = (o < 4096) ? (Wg + (size_t)l * 4194304 + o)
                                 : (Wu + (size_t)l * 4194304 + (o - 4096));
    int e0 = blockIdx.y * 64;
    const float* wp = wb + (size_t)e0 * 4096;
    float4 acc = {0.f, 0.f, 0.f, 0.f};
    #pragma unroll 16
    for (int e = 0; e < 64; e++) {
        float4 w = *(const float4*)wp;
        fma4(acc, xs[e0 + e], w);
        wp += 4096;
    }
    atomicAdd(&g_acc_gu[o + 0], acc.x);
    atomicAdd(&g_acc_gu[o + 1], acc.y);
    atomicAdd(&g_acc_gu[o + 2], acc.z);
    atomicAdd(&g_acc_gu[o + 3], acc.w);
    int gt = (blockIdx.y * 8 + blockIdx.x) * 256 + tid;
    if (gt < 256) g_acc_pg[gt] = 0.f;
}

// ---------------- K7: FF down gemv ----------------
__global__ __launch_bounds__(256) void k_wd(const float* __restrict__ Wd, int l) {
    __shared__ float xs[32];
    int tid = threadIdx.x;
    int e0 = blockIdx.y * 32;
    if (tid < 32) {
        float gv = g_acc_gu[e0 + tid], uv = g_acc_gu[4096 + e0 + tid];
        xs[tid] = gelu_tanh(gv) * uv;
    }
    __syncthreads();
    const float* wp = Wd + (size_t)l * 4194304 + (size_t)e0 * 1024 + tid * 4;
    float4 acc = {0.f, 0.f, 0.f, 0.f};
    #pragma unroll 16
    for (int i = 0; i < 32; i++) {
        float4 w = *(const float4*)wp;
        fma4(acc, xs[i], w);
        wp += 1024;
    }
    int o = tid * 4;
    atomicAdd(&g_acc_mlp[o + 0], acc.x);
    atomicAdd(&g_acc_mlp[o + 1], acc.y);
    atomicAdd(&g_acc_mlp[o + 2], acc.z);
    atomicAdd(&g_acc_mlp[o + 3], acc.w);
    if (blockIdx.y < 4) g_acc_pli[blockIdx.y * 256 + tid] = 0.f;
}

// ---------------- K8: PLI gate gemv ----------------
__global__ __launch_bounds__(256) void k_pli1(const float* __restrict__ Wpg,
                                              const float* __restrict__ ln_postff, int l) {
    __shared__ __align__(16) float xs[1024];
    __shared__ float sred[8];
    __shared__ float4 red[256];
    int tid = threadIdx.x;
    float mv[4];
    float ss = 0.f;
    #pragma unroll
    for (int i = 0; i < 4; i++) { mv[i] = g_acc_mlp[tid + i * 256]; ss += mv[i] * mv[i]; }
    ss = bsum<8>(ss, sred);
    float r = rsqrtf(ss / 1024.f + 1e-6f);
    const float* w = ln_postff + (size_t)l * 1024;
    #pragma unroll
    for (int i = 0; i < 4; i++) {
        int idx = tid + i * 256;
        float h2 = g_h1[idx] + mv[i] * r * (1.f + w[idx]);
        xs[idx] = h2;
        if (blockIdx.y == 0) g_h2[idx] = h2;
    }
    __syncthreads();
    int o4 = tid & 63;
    int sub = tid >> 6;        // 4 subsets of 16 e's
    int eb = blockIdx.y * 64 + sub * 16;
    const float* wp = Wpg + (size_t)l * 262144 + (size_t)eb * 256 + o4 * 4;
    float4 acc = {0.f, 0.f, 0.f, 0.f};
    #pragma unroll
    for (int i = 0; i < 16; i++) {
        float4 wv = *(const float4*)wp;
        fma4(acc, xs[eb + i], wv);
        wp += 256;
    }
    red[tid] = acc;
    __syncthreads();
    if (tid < 64) {
        float4 t = red[tid];
        #pragma unroll
        for (int s = 1; s < 4; s++) {
            float4 u = red[tid + 64 * s];
            t.x += u.x; t.y += u.y; t.z += u.z; t.w += u.w;
        }
        int o = tid * 4;
        atomicAdd(&g_acc_pg[o + 0], t.x);
        atomicAdd(&g_acc_pg[o + 1], t.y);
        atomicAdd(&g_acc_pg[o + 2], t.z);
        atomicAdd(&g_acc_pg[o + 3], t.w);
    }
    for (int z = blockIdx.y * 256 + tid; z < 5120; z += 4096) g_acc_qkv[z] = 0.f;
}

// ---------------- K9: PLI proj gemv ----------------
__global__ __launch_bounds__(256) void k_pli2(const float* __restrict__ Wpp,
                                              const float* __restrict__ plc, int l) {
    __shared__ float xs[32];
    int tid = threadIdx.x;
    int e0 = blockIdx.y * 32;
    if (tid < 32)
        xs[tid] = gelu_tanh(g_acc_pg[e0 + tid]) * plc[(size_t)l * 256 + e0 + tid];
    __syncthreads();
    const float* wp = Wpp + (size_t)l * 262144 + (size_t)e0 * 1024 + tid * 4;
    float4 acc = {0.f, 0.f, 0.f, 0.f};
    #pragma unroll 16
    for (int i = 0; i < 32; i++) {
        float4 w = *(const float4*)wp;
        fma4(acc, xs[i], w);
        wp += 1024;
    }
    int o = tid * 4;
    atomicAdd(&g_acc_pli[o + 0], acc.x);
    atomicAdd(&g_acc_pli[o + 1], acc.y);
    atomicAdd(&g_acc_pli[o + 2], acc.z);
    atomicAdd(&g_acc_pli[o + 3], acc.w);
}

// ---------------- final h ----------------
__global__ __launch_bounds__(256) void k_final(float* __restrict__ out,
                                               const float* __restrict__ ln_ppli,
                                               const float* __restrict__ lscal) {
    __shared__ float sred[8];
    int tid = threadIdx.x;
    const float* w = ln_ppli + (size_t)14 * 1024;
    float pv[4]; float ss = 0.f;
    #pragma unroll
    for (int i = 0; i < 4; i++) { pv[i] = g_acc_pli[tid + i * 256]; ss += pv[i] * pv[i]; }
    ss = bsum<8>(ss, sred);
    float r = rsqrtf(ss / 1024.f + 1e-6f);
    float sc = lscal[14];
    #pragma unroll
    for (int i = 0; i < 4; i++) {
        int idx = tid + i * 256;
        out[idx] = (g_h2[idx] + pv[i] * r * (1.f + w[idx])) * sc;
    }
}

// ---------------- kv outputs (float4) ----------------
__global__ __launch_bounds__(256) void k_copy(float* __restrict__ out,
                                              const float* __restrict__ kv,
                                              const int* __restrict__ pos_ids) {
    int pos = pos_ids[0];
    const float4* kv4 = (const float4*)kv;
    float4* out4 = (float4*)(out + 1024);
    size_t total4 = 786432;
    for (size_t i = (size_t)blockIdx.x * blockDim.x + threadIdx.x; i < total4;
         i += (size_t)gridDim.x * blockDim.x) {
        float4 v;
        if (i < 131072) {
            int j = (int)(i >> 6), d4 = (int)(i & 63);
            v = (j == pos) ? ((const float4*)g_kcur[13])[d4]
                           : kv4[((size_t)13 * 2048 + j) * 128 + d4];
        } else if (i < 262144) {
            size_t t = i - 131072; int j = (int)(t >> 6), d4 = (int)(t & 63);
            v = (j == pos) ? ((const float4*)g_vcur[13])[d4]
                           : kv4[((size_t)28 * 2048 + j) * 128 + d4];
        } else if (i < 524288) {
            size_t t = i - 262144; int j = (int)(t >> 7), d4 = (int)(t & 127);
            v = (j == pos) ? ((const float4*)g_kcur[14])[d4]
                           : kv4[((size_t)14 * 2048 + j) * 128 + d4];
        } else {
            size_t t = i - 524288; int j = (int)(t >> 7), d4 = (int)(t & 127);
            v = (j == pos) ? ((const float4*)g_vcur[14])[d4]
                           : kv4[((size_t)29 * 2048 + j) * 128 + d4];
        }
        out4[i] = v;
    }
}

// ---------------- host ----------------
extern "C" void kernel_launch(void* const* d_in, const int* in_sizes, int n_in,
                              void* d_out, int out_size) {
    const float* embed     = (const float*)d_in[0];
    const float* cos_s     = (const float*)d_in[1];
    const float* sin_s     = (const float*)d_in[2];
    const float* cos_f     = (const float*)d_in[3];
    const float* sin_f     = (const float*)d_in[4];
    const float* ln_in     = (const float*)d_in[5];
    const float* ln_pa     = (const float*)d_in[6];
    const float* ln_pff    = (const float*)d_in[7];
    const float* ln_postff = (const float*)d_in[8];
    const float* ln_ppli   = (const float*)d_in[9];
    const float* qn_w      = (const float*)d_in[10];
    const float* kn_w      = (const float*)d_in[11];
    const float* Wq        = (const float*)d_in[12];
    const float* Wk        = (const float*)d_in[13];
    const float* Wv        = (const float*)d_in[14];
    const float* Wo        = (const float*)d_in[15];
    const float* Wg        = (const float*)d_in[16];
    const float* Wu        = (const float*)d_in[17];
    const float* Wd        = (const float*)d_in[18];
    const float* Wpg       = (const float*)d_in[19];
    const float* Wpp       = (const float*)d_in[20];
    const float* lscal     = (const float*)d_in[21];
    const float* kv        = (const float*)d_in[22];
    const float* plc       = (const float*)d_in[23];
    const float* img       = (const float*)d_in[24];
    const int*   ids       = (const int*)d_in[27];
    const int*   pid       = (const int*)d_in[28];
    float* out = (float*)d_out;

    k_embed<<<1, 256>>>(embed, img, ids);
    for (int l = 0; l < 15; l++) {
        int full = ((l + 1) % 5 == 0);
        int hd = full ? 512 : 256;
        const float* ct = full ? cos_f : cos_s;
        const float* st = full ? sin_f : sin_s;
        k_qkv<<<dim3(full ? 10 : 5, 16), 128>>>(Wq, Wk, Wv, ln_in, ln_ppli, lscal, l, hd);
        k_scores<<<80, 256>>>(kv, qn_w, kn_w, ct, st, pid, l, hd);
        k_probs<<<8, 256>>>(pid);
        k_attnv<<<8, 256>>>(kv, pid, l, hd);
        if (full) k_wo<16><<<dim3(1, 64), 256>>>(Wo, l, hd);
        else      k_wo<32><<<dim3(1, 32), 256>>>(Wo, l, hd);
        k_ff1<<<dim3(8, 16), 256>>>(Wg, Wu, ln_pa, ln_pff, l);
        k_wd<<<dim3(1, 128), 256>>>(Wd, l);
        k_pli1<<<dim3(1, 16), 256>>>(Wpg, ln_postff, l);
        k_pli2<<<dim3(1, 8), 256>>>(Wpp, plc, l);
    }
    k_final<<<1, 256>>>(out, ln_ppli, lscal);
    if (out_size >= 3146752) k_copy<<<1536, 256>>>(out, kv, pid);
}

// round 10
// speedup vs baseline: 1.0116x; 1.0116x over previous
#include <cuda_runtime.h>
#include <math.h>

// ---------------- scratch (device globals; no allocation) ----------------
__device__ float g_h0[1024];
__device__ float g_h1[1024];
__device__ float g_h2[1024];
__device__ float g_acc_qkv[5120];        // [q:8*hd][k:hd][v:hd]
__device__ float g_scores[8 * 2048];     // [h][j] -> probs after k_probs
__device__ __align__(16) float g_attn_part[32 * 4096]; // [row][h*hd+d]
__device__ float g_acc_o[1024];
__device__ float g_acc_gu[8192];         // [g:4096][u:4096]
__device__ float g_acc_mlp[1024];
__device__ float g_acc_pg[256];
__device__ float g_acc_pli[1024];
__device__ __align__(16) float g_kcur[15][512];
__device__ __align__(16) float g_vcur[15][512];

// ---------------- helpers ----------------
template <int NW>
__device__ __forceinline__ float bsum(float v, float* sred) {
    int tid = threadIdx.x;
    #pragma unroll
    for (int o = 16; o; o >>= 1) v += __shfl_xor_sync(0xffffffff, v, o);
    if ((tid & 31) == 0) sred[tid >> 5] = v;
    __syncthreads();
    if (tid == 0) {
        float t = sred[0];
        #pragma unroll
        for (int i = 1; i < NW; i++) t += sred[i];
        sred[0] = t;
    }
    __syncthreads();
    float r = sred[0];
    __syncthreads();
    return r;
}

template <int NW>
__device__ __forceinline__ float bmax(float v, float* sred) {
    int tid = threadIdx.x;
    #pragma unroll
    for (int o = 16; o; o >>= 1) v = fmaxf(v, __shfl_xor_sync(0xffffffff, v, o));
    if ((tid & 31) == 0) sred[tid >> 5] = v;
    __syncthreads();
    if (tid == 0) {
        float t = sred[0];
        #pragma unroll
        for (int i = 1; i < NW; i++) t = fmaxf(t, sred[i]);
        sred[0] = t;
    }
    __syncthreads();
    float r = sred[0];
    __syncthreads();
    return r;
}

__device__ __forceinline__ float gelu_tanh(float x) {
    float x3 = x * x * x;
    return 0.5f * x * (1.f + tanhf(0.7978845608028654f * (x + 0.044715f * x3)));
}

__device__ __forceinline__ void fma4(float4& a, float x, const float4 w) {
    a.x += x * w.x; a.y += x * w.y; a.z += x * w.z; a.w += x * w.w;
}

// ---------------- embed ----------------
__global__ __launch_bounds__(256) void k_embed(const float* __restrict__ embed,
                                               const float* __restrict__ img,
                                               const int* __restrict__ ids) {
    __shared__ float sred[8];
    int tid = threadIdx.x;
    int id = ids[0];
    float iv[4];
    float sa = 0.f;
    #pragma unroll
    for (int i = 0; i < 4; i++) { iv[i] = img[tid + i * 256]; sa += fabsf(iv[i]); }
    sa = bsum<8>(sa, sred);
    bool isimg = sa > 0.f;
    const float* er = embed + (size_t)id * 1024;
    #pragma unroll
    for (int i = 0; i < 4; i++) {
        int idx = tid + i * 256;
        g_h0[idx] = isimg ? iv[i] : er[idx] * 32.0f; // sqrt(1024)=32
    }
    for (int z = tid; z < 5120; z += 256) g_acc_qkv[z] = 0.f;
}

// ---------------- K1: QKV gemv (+ finish previous layer's h) ----------------
__global__ __launch_bounds__(128) void k_qkv(const float* __restrict__ Wq,
                                             const float* __restrict__ Wk,
                                             const float* __restrict__ Wv,
                                             const float* __restrict__ ln_in,
                                             const float* __restrict__ ln_ppli,
                                             const float* __restrict__ lscal,
                                             int l, int hd) {
    __shared__ __align__(16) float xs[1024];
    __shared__ float sred[8];
    int tid = threadIdx.x;
    float h0v[8];
    if (l == 0) {
        #pragma unroll
        for (int i = 0; i < 8; i++) h0v[i] = g_h0[tid + i * 128];
    } else {
        const float* lw = ln_ppli + (size_t)(l - 1) * 1024;
        float pv[8]; float ss = 0.f;
        #pragma unroll
        for (int i = 0; i < 8; i++) { pv[i] = g_acc_pli[tid + i * 128]; ss += pv[i] * pv[i]; }
        ss = bsum<4>(ss, sred);
        float r = rsqrtf(ss / 1024.f + 1e-6f);
        float sc = lscal[l - 1];
        #pragma unroll
        for (int i = 0; i < 8; i++) {
            int idx = tid + i * 128;
            h0v[i] = (g_h2[idx] + pv[i] * r * (1.f + lw[idx])) * sc;
        }
        if (blockIdx.x == 0 && blockIdx.y == 0)
            #pragma unroll
            for (int i = 0; i < 8; i++) g_h0[tid + i * 128] = h0v[i];
    }
    {
        float ss = 0.f;
        #pragma unroll
        for (int i = 0; i < 8; i++) ss += h0v[i] * h0v[i];
        ss = bsum<4>(ss, sred);
        float r = rsqrtf(ss / 1024.f + 1e-6f);
        const float* lw = ln_in + (size_t)l * 1024;
        #pragma unroll
        for (int i = 0; i < 8; i++) { int idx = tid + i * 128; xs[idx] = h0v[i] * r * (1.f + lw[idx]); }
    }
    __syncthreads();

    int o = (blockIdx.x * 128 + tid) * 4;
    int qsize = 8 * hd;
    int lhd = (hd == 512) ? 9 : 8;
    const float* wbase; int stride;
    if (o < qsize) {
        int hh = o >> lhd; int d = o & (hd - 1);
        wbase = Wq + (size_t)l * 4194304 + hh * 512 + d; stride = 4096;
    } else if (o < qsize + hd) {
        wbase = Wk + (size_t)l * 524288 + (o - qsize); stride = 512;
    } else {
        wbase = Wv + (size_t)l * 524288 + (o - qsize - hd); stride = 512;
    }
    int e0 = blockIdx.y * 64;
    const float* wp = wbase + (size_t)e0 * stride;
    float4 acc = {0.f, 0.f, 0.f, 0.f};
    #pragma unroll 16
    for (int e = 0; e < 64; e++) {
        float4 w = *(const float4*)wp;
        fma4(acc, xs[e0 + e], w);
        wp += stride;
    }
    atomicAdd(&g_acc_qkv[o + 0], acc.x);
    atomicAdd(&g_acc_qkv[o + 1], acc.y);
    atomicAdd(&g_acc_qkv[o + 2], acc.z);
    atomicAdd(&g_acc_qkv[o + 3], acc.w);
}

// ---------------- K2: finalize q/k/v (rms+rope) + scores ----------------
__global__ __launch_bounds__(256) void k_scores(const float* __restrict__ kv,
                                                const float* __restrict__ qn_w,
                                                const float* __restrict__ kn_w,
                                                const float* __restrict__ cost,
                                                const float* __restrict__ sint,
                                                const int* __restrict__ pos_ids,
                                                int l, int hd) {
    __shared__ __align__(16) float qf[8 * 512];
    __shared__ __align__(16) float kc[512];
    __shared__ __align__(16) float vc[512];
    __shared__ float sred[8];
    int tid = threadIdx.x, wid = tid >> 5, lane = tid & 31;
    int pos = pos_ids[0];
    int half = hd >> 1;
    int lhd = (hd == 512) ? 9 : 8;
    const float* cr = cost + (size_t)pos * hd;
    const float* sr = sint + (size_t)pos * hd;

    // zero acc_o for K5's atomics
    { int gt = blockIdx.x * 256 + tid; if (gt < 1024) g_acc_o[gt] = 0.f; }

    // q rms per head (warp wid -> head wid)
    {
        const float* qraw = g_acc_qkv + (size_t)wid * hd;
        float ss = 0.f;
        for (int i = lane; i < hd; i += 32) { float v = qraw[i]; ss += v * v; }
        #pragma unroll
        for (int o = 16; o; o >>= 1) ss += __shfl_xor_sync(0xffffffff, ss, o);
        float r = rsqrtf(ss / (float)hd + 1e-6f);
        const float* qw = qn_w + (size_t)l * 512;
        for (int i = lane; i < hd; i += 32) qf[wid * hd + i] = qraw[i] * r * (1.f + qw[i]);
    }
    // k rms
    {
        float ss = 0.f;
        for (int i = tid; i < hd; i += 256) { float v = g_acc_qkv[8 * hd + i]; ss += v * v; }
        ss = bsum<8>(ss, sred);
        float r = rsqrtf(ss / (float)hd + 1e-6f);
        const float* kw = kn_w + (size_t)l * 512;
        for (int i = tid; i < hd; i += 256) kc[i] = g_acc_qkv[8 * hd + i] * r * (1.f + kw[i]);
    }
    // v norm
    {
        float ss = 0.f;
        for (int i = tid; i < hd; i += 256) { float v = g_acc_qkv[9 * hd + i]; ss += v * v; }
        ss = bsum<8>(ss, sred);
        float r = rsqrtf(ss / (float)hd + 1e-6f);
        for (int i = tid; i < hd; i += 256) vc[i] = g_acc_qkv[9 * hd + i] * r;
    }
    __syncthreads();
    // rope q,k (read pairs to regs, sync, write)
    float tq[16]; float tk[2];
    int nq = (8 * hd) / 256;  // 8 or 16
    int nk = hd / 256;        // 1 or 2
    for (int i = 0; i < nq; i++) {
        int idx = tid + i * 256;
        int h = idx >> lhd; int d = idx & (hd - 1);
        float x = qf[idx];
        float rot = (d < half) ? -qf[h * hd + d + half] : qf[h * hd + d - half];
        tq[i] = x * cr[d] + rot * sr[d];
    }
    for (int i = 0; i < nk; i++) {
        int d = tid + i * 256;
        float x = kc[d];
        float rot = (d < half) ? -kc[d + half] : kc[d - half];
        tk[i] = x * cr[d] + rot * sr[d];
    }
    __syncthreads();
    for (int i = 0; i < nq; i++) qf[tid + i * 256] = tq[i];
    for (int i = 0; i < nk; i++) kc[tid + i * 256] = tk[i];
    __syncthreads();
    if (blockIdx.x == 0) {
        for (int i = 0; i < nk; i++) {
            g_kcur[l][tid + i * 256] = kc[tid + i * 256];
            g_vcur[l][tid + i * 256] = vc[tid + i * 256];
        }
    }
    // scores: warp wid handles j = blockIdx.x*8 + wid, stride gridDim.x*8
    int it = hd >> 7; // float4 iterations per lane: 2 or 4
    for (int j = blockIdx.x * 8 + wid; j <= pos; j += gridDim.x * 8) {
        const float4* Kr = (j == pos) ? (const float4*)kc
                                      : (const float4*)(kv + ((size_t)l * 2048 + j) * 512);
        float a[8] = {0, 0, 0, 0, 0, 0, 0, 0};
        #pragma unroll
        for (int t = 0; t < 4; t++) {
            if (t < it) {
                int i4 = lane + t * 32;
                float4 kvv = Kr[i4];
                #pragma unroll
                for (int h = 0; h < 8; h++) {
                    float4 q = *(const float4*)&qf[h * hd + i4 * 4];
                    a[h] += q.x * kvv.x + q.y * kvv.y + q.z * kvv.z + q.w * kvv.w;
                }
            }
        }
        #pragma unroll
        for (int h = 0; h < 8; h++) {
            float t = a[h];
            #pragma unroll
            for (int o = 16; o; o >>= 1) t += __shfl_xor_sync(0xffffffff, t, o);
            if (lane == 0) g_scores[h * 2048 + j] = t;
        }
    }
}

// ---------------- K3: softmax normalize per head (in place) ----------------
__global__ __launch_bounds__(256) void k_probs(const int* __restrict__ pos_ids) {
    __shared__ float sred[8];
    int tid = threadIdx.x;
    int h = blockIdx.x;
    int pos = pos_ids[0];
    float* sc = g_scores + (size_t)h * 2048;
    float mx = -1e30f;
    for (int j = tid; j <= pos; j += 256) mx = fmaxf(mx, sc[j]);
    mx = bmax<8>(mx, sred);
    float se = 0.f;
    for (int j = tid; j <= pos; j += 256) se += __expf(sc[j] - mx);
    se = bsum<8>(se, sred);
    float inv = 1.f / se;
    for (int j = tid; j <= pos; j += 256) sc[j] = __expf(sc[j] - mx) * inv;
    // zero acc_gu for k_ff1
    for (int z = h * 256 + tid; z < 8192; z += 2048) g_acc_gu[z] = 0.f;
}

// ---------------- K4: weighted V, all heads per block (j-chunk partials) ----------------
__global__ __launch_bounds__(256) void k_attnv(const float* __restrict__ kv,
                                               const int* __restrict__ pos_ids,
                                               int l, int hd) {
    int tid = threadIdx.x;
    int pos = pos_ids[0];
    int d4c = hd >> 2;              // 64 or 128
    int d4 = tid & (d4c - 1);
    int sub = (hd == 512) ? (tid >> 7) : (tid >> 6);
    int S = 256 / d4c;              // 2 or 4
    int j0 = blockIdx.x * 256;
    float4 a[8];
    #pragma unroll
    for (int h = 0; h < 8; h++) a[h] = make_float4(0.f, 0.f, 0.f, 0.f);

    const float4* Vb = (const float4*)(kv + (size_t)(15 + l) * 2048 * 512);
    int jmax = (pos < j0 + 255) ? pos : (j0 + 255);
    for (int j = j0 + sub; j <= jmax; j += S) {
        const float4* vr = (j == pos) ? (const float4*)g_vcur[l] : (Vb + (size_t)j * 128);
        float4 v = vr[d4];
        #pragma unroll
        for (int h = 0; h < 8; h++) {
            float p = g_scores[h * 2048 + j];
            fma4(a[h], p, v);
        }
    }
    // write partial row = chunk*S + sub (zeros if no j in range)
    float* op = g_attn_part + (size_t)(blockIdx.x * S + sub) * 4096;
    #pragma unroll
    for (int h = 0; h < 8; h++)
        *(float4*)&op[h * hd + d4 * 4] = a[h];
}

// ---------------- K5: Wo gemv ----------------
template <int NROWS>
__global__ __launch_bounds__(256) void k_wo(const float* __restrict__ Wo, int l, int hd) {
    __shared__ float xs[64];
    int tid = threadIdx.x;
    int i0 = blockIdx.y * 64;
    if (tid < 64) {
        float s = 0.f;
        #pragma unroll
        for (int c = 0; c < NROWS; c++) s += g_attn_part[(size_t)c * 4096 + i0 + tid];
        xs[tid] = s;
    }
    __syncthreads();
    int lhd = (hd == 512) ? 9 : 8;
    int row0 = (i0 >> lhd) * 512 + (i0 & (hd - 1));
    const float* wp = Wo + (size_t)l * 4194304 + (size_t)row0 * 1024 + tid * 4;
    float4 acc = {0.f, 0.f, 0.f, 0.f};
    #pragma unroll 16
    for (int i = 0; i < 64; i++) {
        float4 w = *(const float4*)wp;
        fma4(acc, xs[i], w);
        wp += 1024;
    }
    int o = tid * 4;
    atomicAdd(&g_acc_o[o + 0], acc.x);
    atomicAdd(&g_acc_o[o + 1], acc.y);
    atomicAdd(&g_acc_o[o + 2], acc.z);
    atomicAdd(&g_acc_o[o + 3], acc.w);
    int gt = blockIdx.y * 256 + tid;
    if (gt < 1024) g_acc_mlp[gt] = 0.f;
}

// ---------------- K6: FF gate+up gemv ----------------
__global__ __launch_bounds__(256) void k_ff1(const float* __restrict__ Wg,
                                             const float* __restrict__ Wu,
                                             const float* __restrict__ ln_pa,
                                             const float* __restrict__ ln_pff, int l) {
    __shared__ __align__(16) float xs[1024];
    __shared__ float sred[8];
    int tid = threadIdx.x;
    float ov[4], h1v[4];
    float ss = 0.f;
    #pragma unroll
    for (int i = 0; i < 4; i++) { ov[i] = g_acc_o[tid + i * 256]; ss += ov[i] * ov[i]; }
    ss = bsum<8>(ss, sred);
    float r = rsqrtf(ss / 1024.f + 1e-6f);
    const float* wpa = ln_pa + (size_t)l * 1024;
    #pragma unroll
    for (int i = 0; i < 4; i++) { int idx = tid + i * 256; h1v[i] = g_h0[idx] + ov[i] * r * (1.f + wpa[idx]); }
    if (blockIdx.x == 0 && blockIdx.y == 0)
        #pragma unroll
        for (int i = 0; i < 4; i++) g_h1[tid + i * 256] = h1v[i];
    float s2 = 0.f;
    #pragma unroll
    for (int i = 0; i < 4; i++) s2 += h1v[i] * h1v[i];
    s2 = bsum<8>(s2, sred);
    float r2 = rsqrtf(s2 / 1024.f + 1e-6f);
    const float* wpf = ln_pff + (size_t)l * 1024;
    #pragma unroll
    for (int i = 0; i < 4; i++) { int idx = tid + i * 256; xs[idx] = h1v[i] * r2 * (1.f + wpf[idx]); }
    __syncthreads();

    int o = (blockIdx.x * 256 + tid) * 4;  // 0..8191
    const float* wb = (o < 4096) ? (Wg + (size_t)l * 4194304 + o)
                                 : (Wu + (size_t)l * 4194304 + (o - 4096));
    int e0 = blockIdx.y * 64;
    const float* wp = wb + (size_t)e0 * 4096;
    float4 acc = {0.f, 0.f, 0.f, 0.f};
    #pragma unroll 16
    for (int e = 0; e < 64; e++) {
        float4 w = *(const float4*)wp;
        fma4(acc, xs[e0 + e], w);
        wp += 4096;
    }
    atomicAdd(&g_acc_gu[o + 0], acc.x);
    atomicAdd(&g_acc_gu[o + 1], acc.y);
    atomicAdd(&g_acc_gu[o + 2], acc.z);
    atomicAdd(&g_acc_gu[o + 3], acc.w);
    int gt = (blockIdx.y * 8 + blockIdx.x) * 256 + tid;
    if (gt < 256) g_acc_pg[gt] = 0.f;
}

// ---------------- K7: FF down gemv ----------------
__global__ __launch_bounds__(256) void k_wd(const float* __restrict__ Wd, int l) {
    __shared__ float xs[32];
    int tid = threadIdx.x;
    int e0 = blockIdx.y * 32;
    if (tid < 32) {
        float gv = g_acc_gu[e0 + tid], uv = g_acc_gu[4096 + e0 + tid];
        xs[tid] = gelu_tanh(gv) * uv;
    }
    __syncthreads();
    const float* wp = Wd + (size_t)l * 4194304 + (size_t)e0 * 1024 + tid * 4;
    float4 acc = {0.f, 0.f, 0.f, 0.f};
    #pragma unroll 16
    for (int i = 0; i < 32; i++) {
        float4 w = *(const float4*)wp;
        fma4(acc, xs[i], w);
        wp += 1024;
    }
    int o = tid * 4;
    atomicAdd(&g_acc_mlp[o + 0], acc.x);
    atomicAdd(&g_acc_mlp[o + 1], acc.y);
    atomicAdd(&g_acc_mlp[o + 2], acc.z);
    atomicAdd(&g_acc_mlp[o + 3], acc.w);
    if (blockIdx.y < 4) g_acc_pli[blockIdx.y * 256 + tid] = 0.f;
}

// ---------------- K8: PLI gate gemv ----------------
__global__ __launch_bounds__(256) void k_pli1(const float* __restrict__ Wpg,
                                              const float* __restrict__ ln_postff, int l) {
    __shared__ __align__(16) float xs[1024];
    __shared__ float sred[8];
    __shared__ float4 red[256];
    int tid = threadIdx.x;
    float mv[4];
    float ss = 0.f;
    #pragma unroll
    for (int i = 0; i < 4; i++) { mv[i] = g_acc_mlp[tid + i * 256]; ss += mv[i] * mv[i]; }
    ss = bsum<8>(ss, sred);
    float r = rsqrtf(ss / 1024.f + 1e-6f);
    const float* w = ln_postff + (size_t)l * 1024;
    #pragma unroll
    for (int i = 0; i < 4; i++) {
        int idx = tid + i * 256;
        float h2 = g_h1[idx] + mv[i] * r * (1.f + w[idx]);
        xs[idx] = h2;
        if (blockIdx.y == 0) g_h2[idx] = h2;
    }
    __syncthreads();
    int o4 = tid & 63;
    int sub = tid >> 6;        // 4 subsets of 16 e's
    int eb = blockIdx.y * 64 + sub * 16;
    const float* wp = Wpg + (size_t)l * 262144 + (size_t)eb * 256 + o4 * 4;
    float4 acc = {0.f, 0.f, 0.f, 0.f};
    #pragma unroll
    for (int i = 0; i < 16; i++) {
        float4 wv = *(const float4*)wp;
        fma4(acc, xs[eb + i], wv);
        wp += 256;
    }
    red[tid] = acc;
    __syncthreads();
    if (tid < 64) {
        float4 t = red[tid];
        #pragma unroll
        for (int s = 1; s < 4; s++) {
            float4 u = red[tid + 64 * s];
            t.x += u.x; t.y += u.y; t.z += u.z; t.w += u.w;
        }
        int o = tid * 4;
        atomicAdd(&g_acc_pg[o + 0], t.x);
        atomicAdd(&g_acc_pg[o + 1], t.y);
        atomicAdd(&g_acc_pg[o + 2], t.z);
        atomicAdd(&g_acc_pg[o + 3], t.w);
    }
    for (int z = blockIdx.y * 256 + tid; z < 5120; z += 4096) g_acc_qkv[z] = 0.f;
}

// ---------------- K9: PLI proj gemv ----------------
__global__ __launch_bounds__(256) void k_pli2(const float* __restrict__ Wpp,
                                              const float* __restrict__ plc, int l) {
    __shared__ float xs[32];
    int tid = threadIdx.x;
    int e0 = blockIdx.y * 32;
    if (tid < 32)
        xs[tid] = gelu_tanh(g_acc_pg[e0 + tid]) * plc[(size_t)l * 256 + e0 + tid];
    __syncthreads();
    const float* wp = Wpp + (size_t)l * 262144 + (size_t)e0 * 1024 + tid * 4;
    float4 acc = {0.f, 0.f, 0.f, 0.f};
    #pragma unroll 16
    for (int i = 0; i < 32; i++) {
        float4 w = *(const float4*)wp;
        fma4(acc, xs[i], w);
        wp += 1024;
    }
    int o = tid * 4;
    atomicAdd(&g_acc_pli[o + 0], acc.x);
    atomicAdd(&g_acc_pli[o + 1], acc.y);
    atomicAdd(&g_acc_pli[o + 2], acc.z);
    atomicAdd(&g_acc_pli[o + 3], acc.w);
}

// ---------------- final h ----------------
__global__ __launch_bounds__(256) void k_final(float* __restrict__ out,
                                               const float* __restrict__ ln_ppli,
                                               const float* __restrict__ lscal) {
    __shared__ float sred[8];
    int tid = threadIdx.x;
    const float* w = ln_ppli + (size_t)14 * 1024;
    float pv[4]; float ss = 0.f;
    #pragma unroll
    for (int i = 0; i < 4; i++) { pv[i] = g_acc_pli[tid + i * 256]; ss += pv[i] * pv[i]; }
    ss = bsum<8>(ss, sred);
    float r = rsqrtf(ss / 1024.f + 1e-6f);
    float sc = lscal[14];
    #pragma unroll
    for (int i = 0; i < 4; i++) {
        int idx = tid + i * 256;
        out[idx] = (g_h2[idx] + pv[i] * r * (1.f + w[idx])) * sc;
    }
}

// ---------------- kv outputs (float4) ----------------
__global__ __launch_bounds__(256) void k_copy(float* __restrict__ out,
                                              const float* __restrict__ kv,
                                              const int* __restrict__ pos_ids) {
    int pos = pos_ids[0];
    const float4* kv4 = (const float4*)kv;
    float4* out4 = (float4*)(out + 1024);
    size_t total4 = 786432;
    for (size_t i = (size_t)blockIdx.x * blockDim.x + threadIdx.x; i < total4;
         i += (size_t)gridDim.x * blockDim.x) {
        float4 v;
        if (i < 131072) {
            int j = (int)(i >> 6), d4 = (int)(i & 63);
            v = (j == pos) ? ((const float4*)g_kcur[13])[d4]
                           : kv4[((size_t)13 * 2048 + j) * 128 + d4];
        } else if (i < 262144) {
            size_t t = i - 131072; int j = (int)(t >> 6), d4 = (int)(t & 63);
            v = (j == pos) ? ((const float4*)g_vcur[13])[d4]
                           : kv4[((size_t)28 * 2048 + j) * 128 + d4];
        } else if (i < 524288) {
            size_t t = i - 262144; int j = (int)(t >> 7), d4 = (int)(t & 127);
            v = (j == pos) ? ((const float4*)g_kcur[14])[d4]
                           : kv4[((size_t)14 * 2048 + j) * 128 + d4];
        } else {
            size_t t = i - 524288; int j = (int)(t >> 7), d4 = (int)(t & 127);
            v = (j == pos) ? ((const float4*)g_vcur[14])[d4]
                           : kv4[((size_t)29 * 2048 + j) * 128 + d4];
        }
        out4[i] = v;
    }
}

// ---------------- host ----------------
extern "C" void kernel_launch(void* const* d_in, const int* in_sizes, int n_in,
                              void* d_out, int out_size) {
    const float* embed     = (const float*)d_in[0];
    const float* cos_s     = (const float*)d_in[1];
    const float* sin_s     = (const float*)d_in[2];
    const float* cos_f     = (const float*)d_in[3];
    const float* sin_f     = (const float*)d_in[4];
    const float* ln_in     = (const float*)d_in[5];
    const float* ln_pa     = (const float*)d_in[6];
    const float* ln_pff    = (const float*)d_in[7];
    const float* ln_postff = (const float*)d_in[8];
    const float* ln_ppli   = (const float*)d_in[9];
    const float* qn_w      = (const float*)d_in[10];
    const float* kn_w      = (const float*)d_in[11];
    const float* Wq        = (const float*)d_in[12];
    const float* Wk        = (const float*)d_in[13];
    const float* Wv        = (const float*)d_in[14];
    const float* Wo        = (const float*)d_in[15];
    const float* Wg        = (const float*)d_in[16];
    const float* Wu        = (const float*)d_in[17];
    const float* Wd        = (const float*)d_in[18];
    const float* Wpg       = (const float*)d_in[19];
    const float* Wpp       = (const float*)d_in[20];
    const float* lscal     = (const float*)d_in[21];
    const float* kv        = (const float*)d_in[22];
    const float* plc       = (const float*)d_in[23];
    const float* img       = (const float*)d_in[24];
    const int*   ids       = (const int*)d_in[27];
    const int*   pid       = (const int*)d_in[28];
    float* out = (float*)d_out;

    k_embed<<<1, 256>>>(embed, img, ids);
    for (int l = 0; l < 15; l++) {
        int full = ((l + 1) % 5 == 0);
        int hd = full ? 512 : 256;
        const float* ct = full ? cos_f : cos_s;
        const float* st = full ? sin_f : sin_s;
        k_qkv<<<dim3(full ? 10 : 5, 16), 128>>>(Wq, Wk, Wv, ln_in, ln_ppli, lscal, l, hd);
        k_scores<<<80, 256>>>(kv, qn_w, kn_w, ct, st, pid, l, hd);
        k_probs<<<8, 256>>>(pid);
        k_attnv<<<8, 256>>>(kv, pid, l, hd);
        if (full) k_wo<16><<<dim3(1, 64), 256>>>(Wo, l, hd);
        else      k_wo<32><<<dim3(1, 32), 256>>>(Wo, l, hd);
        k_ff1<<<dim3(8, 16), 256>>>(Wg, Wu, ln_pa, ln_pff, l);
        k_wd<<<dim3(1, 128), 256>>>(Wd, l);
        k_pli1<<<dim3(1, 16), 256>>>(Wpg, ln_postff, l);
        k_pli2<<<dim3(1, 8), 256>>>(Wpp, plc, l);
    }
    k_final<<<1, 256>>>(out, ln_ppli, lscal);
    if (out_size >= 3146752) k_copy<<<1536, 256>>>(out, kv, pid);
}

// round 11
// speedup vs baseline: 1.5856x; 1.5675x over previous
#include <cuda_runtime.h>
#include <math.h>

#define NB 296
#define NT (NB * 256)

// ---------------- scratch (device globals; no allocation) ----------------
__device__ float g_h0[1024], g_h1[1024], g_h2[1024];
__device__ float g_acc_qkv[5120];
__device__ float g_scores[8 * 2048];
__device__ __align__(16) float g_acc_attn[4096];
__device__ float g_acc_o[1024];
__device__ float g_acc_gu[8192];
__device__ float g_acc_mlp[1024];
__device__ float g_acc_pg[256];
__device__ float g_acc_pli[1024];
__device__ __align__(16) float g_vcur[512];
__device__ __align__(16) float g_k13[256], g_v13[256], g_k14[512], g_v14[512];
__device__ unsigned g_cnt = 0, g_gen = 0;

// ---------------- grid barrier (counter + generation) ----------------
__device__ __forceinline__ void gridbar() {
    __syncthreads();
    if (threadIdx.x == 0) {
        volatile unsigned* vg = &g_gen;
        unsigned gen = *vg;               // read BEFORE arriving
        __threadfence();
        if (atomicAdd(&g_cnt, 1u) == NB - 1) {
            g_cnt = 0;
            __threadfence();
            *vg = gen + 1;
        } else {
            while (*vg == gen) { __nanosleep(64); }
        }
        __threadfence();
    }
    __syncthreads();
}

// ---------------- helpers ----------------
__device__ __forceinline__ float bsum(float v, float* sred) {
    int tid = threadIdx.x;
    #pragma unroll
    for (int o = 16; o; o >>= 1) v += __shfl_xor_sync(0xffffffff, v, o);
    if ((tid & 31) == 0) sred[tid >> 5] = v;
    __syncthreads();
    if (tid == 0) {
        float t = sred[0];
        #pragma unroll
        for (int i = 1; i < 8; i++) t += sred[i];
        sred[0] = t;
    }
    __syncthreads();
    float r = sred[0];
    __syncthreads();
    return r;
}

__device__ __forceinline__ float gelu_tanh(float x) {
    float x3 = x * x * x;
    return 0.5f * x * (1.f + tanhf(0.7978845608028654f * (x + 0.044715f * x3)));
}

__device__ __forceinline__ void fma4(float4& a, float x, const float4 w) {
    a.x += x * w.x; a.y += x * w.y; a.z += x * w.z; a.w += x * w.w;
}

__device__ __forceinline__ void atomic4(float* dst, float4 a) {
    atomicAdd(dst + 0, a.x);
    atomicAdd(dst + 1, a.y);
    atomicAdd(dst + 2, a.z);
    atomicAdd(dst + 3, a.w);
}

// ---------------- the megakernel ----------------
__global__ __launch_bounds__(256, 2) void mega(
    const float* __restrict__ embed,
    const float* __restrict__ cos_s, const float* __restrict__ sin_s,
    const float* __restrict__ cos_f, const float* __restrict__ sin_f,
    const float* __restrict__ ln_in, const float* __restrict__ ln_pa,
    const float* __restrict__ ln_pff, const float* __restrict__ ln_postff,
    const float* __restrict__ ln_ppli,
    const float* __restrict__ qn_w, const float* __restrict__ kn_w,
    const float* __restrict__ Wq, const float* __restrict__ Wk,
    const float* __restrict__ Wv, const float* __restrict__ Wo,
    const float* __restrict__ Wg, const float* __restrict__ Wu,
    const float* __restrict__ Wd, const float* __restrict__ Wpg,
    const float* __restrict__ Wpp,
    const float* __restrict__ lscal, const float* __restrict__ kv,
    const float* __restrict__ plc, const float* __restrict__ img,
    const int* __restrict__ ids, const int* __restrict__ pid,
    float* __restrict__ out, int do_copy)
{
    __shared__ __align__(16) float xs[4096];   // qf in scores stage; x-vector otherwise
    __shared__ __align__(16) float kc[512];
    __shared__ __align__(16) float vc[512];
    __shared__ float sred[8];
    __shared__ float sstat[16];                // mx[8], inv[8]

    int tid = threadIdx.x, bid = blockIdx.x;
    int gtid = bid * 256 + tid;
    int wid = tid >> 5, lane = tid & 31;
    int pos = pid[0];

    // ================= S0: embed + zero acc_qkv =================
    {
        int id = ids[0];
        float iv[4]; float sa = 0.f;
        #pragma unroll
        for (int i = 0; i < 4; i++) { iv[i] = img[tid + i * 256]; sa += fabsf(iv[i]); }
        sa = bsum(sa, sred);
        if (bid == 0) {
            const float* er = embed + (size_t)id * 1024;
            bool isimg = sa > 0.f;
            #pragma unroll
            for (int i = 0; i < 4; i++) {
                int idx = tid + i * 256;
                g_h0[idx] = isimg ? iv[i] : er[idx] * 32.0f;
            }
        }
        for (int z = gtid; z < 5120; z += NT) g_acc_qkv[z] = 0.f;
    }
    gridbar();

    for (int l = 0; l < 15; l++) {
        int full = ((l + 1) % 5 == 0);
        int hd = full ? 512 : 256;
        int lhd = full ? 9 : 8;
        const float* ct = full ? cos_f : cos_s;
        const float* st = full ? sin_f : sin_s;

        // ================= S1: h-finish + rms + QKV gemv =================
        {
            float h0v[4];
            if (l == 0) {
                #pragma unroll
                for (int i = 0; i < 4; i++) h0v[i] = g_h0[tid + i * 256];
            } else {
                const float* lw = ln_ppli + (size_t)(l - 1) * 1024;
                float pv[4]; float ss = 0.f;
                #pragma unroll
                for (int i = 0; i < 4; i++) { pv[i] = g_acc_pli[tid + i * 256]; ss += pv[i] * pv[i]; }
                ss = bsum(ss, sred);
                float r = rsqrtf(ss / 1024.f + 1e-6f);
                float sc = lscal[l - 1];
                #pragma unroll
                for (int i = 0; i < 4; i++) {
                    int idx = tid + i * 256;
                    h0v[i] = (g_h2[idx] + pv[i] * r * (1.f + lw[idx])) * sc;
                }
                if (bid == 0)
                    #pragma unroll
                    for (int i = 0; i < 4; i++) g_h0[tid + i * 256] = h0v[i];
            }
            {
                float ss = 0.f;
                #pragma unroll
                for (int i = 0; i < 4; i++) ss += h0v[i] * h0v[i];
                ss = bsum(ss, sred);
                float r = rsqrtf(ss / 1024.f + 1e-6f);
                const float* lw = ln_in + (size_t)l * 1024;
                #pragma unroll
                for (int i = 0; i < 4; i++) { int idx = tid + i * 256; xs[idx] = h0v[i] * r * (1.f + lw[idx]); }
            }
            __syncthreads();

            int O4 = (10 * hd) >> 2;          // 640 / 1280
            int total = O4 << 6;              // KC=64, chunk=16
            int qs = 8 * hd;
            for (int t = gtid; t < total; t += NT) {
                int c = t / O4; int o4 = t - c * O4;
                int o = o4 << 2;
                const float* wb; int stride;
                if (o < qs) {
                    int hh = o >> lhd, d = o & (hd - 1);
                    wb = Wq + (size_t)l * 4194304 + hh * 512 + d; stride = 4096;
                } else if (o < qs + hd) {
                    wb = Wk + (size_t)l * 524288 + (o - qs); stride = 512;
                } else {
                    wb = Wv + (size_t)l * 524288 + (o - qs - hd); stride = 512;
                }
                int e0 = c << 4;
                const float* wp = wb + (size_t)e0 * stride;
                float4 acc = {0.f, 0.f, 0.f, 0.f};
                #pragma unroll
                for (int e = 0; e < 16; e++) { float4 w = *(const float4*)wp; fma4(acc, xs[e0 + e], w); wp += stride; }
                atomic4(&g_acc_qkv[o], acc);
            }
        }
        gridbar();

        // ================= S2: q/k/v finalize + rope + scores =================
        {
            for (int z = gtid; z < 1024; z += NT) g_acc_pli[z] = 0.f;
            for (int z = gtid; z < 4096; z += NT) g_acc_attn[z] = 0.f;

            float* qf = xs;
            int half = hd >> 1;
            const float* cr = ct + (size_t)pos * hd;
            const float* sr = st + (size_t)pos * hd;
            // q rms per head
            {
                const float* qraw = g_acc_qkv + (size_t)wid * hd;
                float ss = 0.f;
                for (int i = lane; i < hd; i += 32) { float v = qraw[i]; ss += v * v; }
                #pragma unroll
                for (int o = 16; o; o >>= 1) ss += __shfl_xor_sync(0xffffffff, ss, o);
                float r = rsqrtf(ss / (float)hd + 1e-6f);
                const float* qw = qn_w + (size_t)l * 512;
                for (int i = lane; i < hd; i += 32) qf[wid * hd + i] = qraw[i] * r * (1.f + qw[i]);
            }
            // k rms
            {
                float ss = 0.f;
                for (int i = tid; i < hd; i += 256) { float v = g_acc_qkv[8 * hd + i]; ss += v * v; }
                ss = bsum(ss, sred);
                float r = rsqrtf(ss / (float)hd + 1e-6f);
                const float* kw = kn_w + (size_t)l * 512;
                for (int i = tid; i < hd; i += 256) kc[i] = g_acc_qkv[8 * hd + i] * r * (1.f + kw[i]);
            }
            // v norm
            {
                float ss = 0.f;
                for (int i = tid; i < hd; i += 256) { float v = g_acc_qkv[9 * hd + i]; ss += v * v; }
                ss = bsum(ss, sred);
                float r = rsqrtf(ss / (float)hd + 1e-6f);
                for (int i = tid; i < hd; i += 256) vc[i] = g_acc_qkv[9 * hd + i] * r;
            }
            __syncthreads();
            // rope (static-index regs to avoid local memory)
            float tq[16], tk[2];
            int nq = (8 * hd) >> 8, nk = hd >> 8;
            #pragma unroll
            for (int i = 0; i < 16; i++) if (i < nq) {
                int idx = tid + i * 256;
                int h = idx >> lhd, d = idx & (hd - 1);
                float x = qf[idx];
                float rot = (d < half) ? -qf[h * hd + d + half] : qf[h * hd + d - half];
                tq[i] = x * cr[d] + rot * sr[d];
            }
            #pragma unroll
            for (int i = 0; i < 2; i++) if (i < nk) {
                int d = tid + i * 256;
                float x = kc[d];
                float rot = (d < half) ? -kc[d + half] : kc[d - half];
                tk[i] = x * cr[d] + rot * sr[d];
            }
            __syncthreads();
            #pragma unroll
            for (int i = 0; i < 16; i++) if (i < nq) qf[tid + i * 256] = tq[i];
            #pragma unroll
            for (int i = 0; i < 2; i++) if (i < nk) kc[tid + i * 256] = tk[i];
            __syncthreads();
            if (bid == 0) {
                #pragma unroll
                for (int i = 0; i < 2; i++) if (i < nk) g_vcur[tid + i * 256] = vc[tid + i * 256];
                if (l == 13) { g_k13[tid] = kc[tid]; g_v13[tid] = vc[tid]; }
                if (l == 14) {
                    #pragma unroll
                    for (int i = 0; i < 2; i++) {
                        g_k14[tid + i * 256] = kc[tid + i * 256];
                        g_v14[tid + i * 256] = vc[tid + i * 256];
                    }
                }
            }
            // scores
            int it = hd >> 7;
            for (int j = bid * 8 + wid; j <= pos; j += NB * 8) {
                const float4* Kr = (j == pos) ? (const float4*)kc
                                              : (const float4*)(kv + ((size_t)l * 2048 + j) * 512);
                float a[8] = {0, 0, 0, 0, 0, 0, 0, 0};
                #pragma unroll
                for (int t = 0; t < 4; t++) if (t < it) {
                    int i4 = lane + t * 32;
                    float4 kvv = Kr[i4];
                    #pragma unroll
                    for (int h = 0; h < 8; h++) {
                        float4 q = *(const float4*)&qf[h * hd + i4 * 4];
                        a[h] += q.x * kvv.x + q.y * kvv.y + q.z * kvv.z + q.w * kvv.w;
                    }
                }
                #pragma unroll
                for (int h = 0; h < 8; h++) {
                    float t = a[h];
                    #pragma unroll
                    for (int o = 16; o; o >>= 1) t += __shfl_xor_sync(0xffffffff, t, o);
                    if (lane == 0) g_scores[h * 2048 + j] = t;
                }
            }
        }
        gridbar();

        // ================= S4: softmax stats (redundant) + weighted V =================
        {
            {
                const float* sc = g_scores + (size_t)wid * 2048;
                float mx = -1e30f;
                for (int j = lane; j <= pos; j += 32) mx = fmaxf(mx, sc[j]);
                #pragma unroll
                for (int o = 16; o; o >>= 1) mx = fmaxf(mx, __shfl_xor_sync(0xffffffff, mx, o));
                float se = 0.f;
                for (int j = lane; j <= pos; j += 32) se += __expf(sc[j] - mx);
                #pragma unroll
                for (int o = 16; o; o >>= 1) se += __shfl_xor_sync(0xffffffff, se, o);
                if (lane == 0) { sstat[wid] = mx; sstat[8 + wid] = 1.f / se; }
            }
            __syncthreads();
            int ld4 = lhd - 2;
            int D4m = (hd >> 2) - 1;
            int NC = (pos + 32) >> 5;        // ceil((pos+1)/32)
            int total = NC << ld4;
            const float4* Vb = (const float4*)(kv + (size_t)(15 + l) * 2048 * 512);
            float mx0 = sstat[0], mx1 = sstat[1], mx2 = sstat[2], mx3 = sstat[3];
            float mx4 = sstat[4], mx5 = sstat[5], mx6 = sstat[6], mx7 = sstat[7];
            float iv0 = sstat[8], iv1 = sstat[9], iv2 = sstat[10], iv3 = sstat[11];
            float iv4 = sstat[12], iv5 = sstat[13], iv6 = sstat[14], iv7 = sstat[15];
            for (int t = gtid; t < total; t += NT) {
                int c = t >> ld4; int d4 = t & D4m;
                float4 a[8];
                #pragma unroll
                for (int h = 0; h < 8; h++) a[h] = make_float4(0.f, 0.f, 0.f, 0.f);
                int j0 = c * 32;
                int jm = (pos < j0 + 31) ? pos : (j0 + 31);
                for (int j = j0; j <= jm; j++) {
                    const float4* vr = (j == pos) ? (const float4*)g_vcur : (Vb + (size_t)j * 128);
                    float4 v = vr[d4];
                    fma4(a[0], __expf(g_scores[0 * 2048 + j] - mx0) * iv0, v);
                    fma4(a[1], __expf(g_scores[1 * 2048 + j] - mx1) * iv1, v);
                    fma4(a[2], __expf(g_scores[2 * 2048 + j] - mx2) * iv2, v);
                    fma4(a[3], __expf(g_scores[3 * 2048 + j] - mx3) * iv3, v);
                    fma4(a[4], __expf(g_scores[4 * 2048 + j] - mx4) * iv4, v);
                    fma4(a[5], __expf(g_scores[5 * 2048 + j] - mx5) * iv5, v);
                    fma4(a[6], __expf(g_scores[6 * 2048 + j] - mx6) * iv6, v);
                    fma4(a[7], __expf(g_scores[7 * 2048 + j] - mx7) * iv7, v);
                }
                #pragma unroll
                for (int h = 0; h < 8; h++) atomic4(&g_acc_attn[h * hd + d4 * 4], a[h]);
            }
            for (int z = gtid; z < 1024; z += NT) g_acc_o[z] = 0.f;
        }
        gridbar();

        // ================= S5: Wo gemv =================
        {
            int N = 8 * hd;
            for (int i = tid; i < N; i += 256) xs[i] = g_acc_attn[i];
            __syncthreads();
            int KC = N >> 5;                 // chunk = 32
            int total = KC << 8;
            for (int t = gtid; t < total; t += NT) {
                int o4 = t & 255; int c = t >> 8;
                int i0 = c << 5;
                int row0 = (i0 >> lhd) * 512 + (i0 & (hd - 1));
                const float* wp = Wo + (size_t)l * 4194304 + (size_t)row0 * 1024 + (o4 << 2);
                float4 acc = {0.f, 0.f, 0.f, 0.f};
                #pragma unroll
                for (int i = 0; i < 32; i++) { float4 w = *(const float4*)wp; fma4(acc, xs[i0 + i], w); wp += 1024; }
                atomic4(&g_acc_o[o4 << 2], acc);
            }
            for (int z = gtid; z < 8192; z += NT) g_acc_gu[z] = 0.f;
        }
        gridbar();

        // ================= S6: residual + rms + FF gate/up gemv =================
        {
            float ov[4], h1v[4];
            float ss = 0.f;
            #pragma unroll
            for (int i = 0; i < 4; i++) { ov[i] = g_acc_o[tid + i * 256]; ss += ov[i] * ov[i]; }
            ss = bsum(ss, sred);
            float r = rsqrtf(ss / 1024.f + 1e-6f);
            const float* wpa = ln_pa + (size_t)l * 1024;
            #pragma unroll
            for (int i = 0; i < 4; i++) { int idx = tid + i * 256; h1v[i] = g_h0[idx] + ov[i] * r * (1.f + wpa[idx]); }
            if (bid == 0)
                #pragma unroll
                for (int i = 0; i < 4; i++) g_h1[tid + i * 256] = h1v[i];
            float s2 = 0.f;
            #pragma unroll
            for (int i = 0; i < 4; i++) s2 += h1v[i] * h1v[i];
            s2 = bsum(s2, sred);
            float r2 = rsqrtf(s2 / 1024.f + 1e-6f);
            const float* wpf = ln_pff + (size_t)l * 1024;
            #pragma unroll
            for (int i = 0; i < 4; i++) { int idx = tid + i * 256; xs[idx] = h1v[i] * r2 * (1.f + wpf[idx]); }
            __syncthreads();

            int total = 2048 << 4;           // O4=2048, KC=16 chunk 64
            for (int t = gtid; t < total; t += NT) {
                int o4 = t & 2047; int c = t >> 11;
                int o = o4 << 2;
                const float* wb = (o < 4096) ? (Wg + (size_t)l * 4194304 + o)
                                             : (Wu + (size_t)l * 4194304 + (o - 4096));
                int e0 = c << 6;
                const float* wp = wb + (size_t)e0 * 4096;
                float4 acc = {0.f, 0.f, 0.f, 0.f};
                #pragma unroll 16
                for (int e = 0; e < 64; e++) { float4 w = *(const float4*)wp; fma4(acc, xs[e0 + e], w); wp += 4096; }
                atomic4(&g_acc_gu[o], acc);
            }
            for (int z = gtid; z < 1024; z += NT) g_acc_mlp[z] = 0.f;
        }
        gridbar();

        // ================= S7: gelu*up + FF down gemv =================
        {
            for (int i = tid; i < 4096; i += 256)
                xs[i] = gelu_tanh(g_acc_gu[i]) * g_acc_gu[4096 + i];
            __syncthreads();
            int total = 128 << 8;            // O4=256, KC=128 chunk 32
            for (int t = gtid; t < total; t += NT) {
                int o4 = t & 255; int c = t >> 8;
                int i0 = c << 5;
                const float* wp = Wd + (size_t)l * 4194304 + (size_t)i0 * 1024 + (o4 << 2);
                float4 acc = {0.f, 0.f, 0.f, 0.f};
                #pragma unroll
                for (int i = 0; i < 32; i++) { float4 w = *(const float4*)wp; fma4(acc, xs[i0 + i], w); wp += 1024; }
                atomic4(&g_acc_mlp[o4 << 2], acc);
            }
            for (int z = gtid; z < 256; z += NT) g_acc_pg[z] = 0.f;
        }
        gridbar();

        // ================= S8: residual + rms + PLI gate gemv =================
        {
            float mv[4];
            float ss = 0.f;
            #pragma unroll
            for (int i = 0; i < 4; i++) { mv[i] = g_acc_mlp[tid + i * 256]; ss += mv[i] * mv[i]; }
            ss = bsum(ss, sred);
            float r = rsqrtf(ss / 1024.f + 1e-6f);
            const float* w = ln_postff + (size_t)l * 1024;
            #pragma unroll
            for (int i = 0; i < 4; i++) {
                int idx = tid + i * 256;
                float h2 = g_h1[idx] + mv[i] * r * (1.f + w[idx]);
                xs[idx] = h2;
                if (bid == 0) g_h2[idx] = h2;
            }
            __syncthreads();
            int total = 64 << 6;             // O4=64, KC=64 chunk 16
            for (int t = gtid; t < total; t += NT) {
                int o4 = t & 63; int c = t >> 6;
                int e0 = c << 4;
                const float* wp = Wpg + (size_t)l * 262144 + (size_t)e0 * 256 + (o4 << 2);
                float4 acc = {0.f, 0.f, 0.f, 0.f};
                #pragma unroll
                for (int e = 0; e < 16; e++) { float4 wv = *(const float4*)wp; fma4(acc, xs[e0 + e], wv); wp += 256; }
                atomic4(&g_acc_pg[o4 << 2], acc);
            }
            for (int z = gtid; z < 5120; z += NT) g_acc_qkv[z] = 0.f;
        }
        gridbar();

        // ================= S9: PLI proj gemv =================
        {
            xs[tid] = gelu_tanh(g_acc_pg[tid]) * plc[(size_t)l * 256 + tid];
            __syncthreads();
            int total = 256 << 5;            // O4=256, KC=32 chunk 8
            for (int t = gtid; t < total; t += NT) {
                int o4 = t & 255; int c = t >> 8;
                int e0 = c << 3;
                const float* wp = Wpp + (size_t)l * 262144 + (size_t)e0 * 1024 + (o4 << 2);
                float4 acc = {0.f, 0.f, 0.f, 0.f};
                #pragma unroll
                for (int e = 0; e < 8; e++) { float4 w = *(const float4*)wp; fma4(acc, xs[e0 + e], w); wp += 1024; }
                atomic4(&g_acc_pli[o4 << 2], acc);
            }
        }
        gridbar();
    }

    // ================= final: h out + kv copies =================
    if (bid == 0) {
        const float* w = ln_ppli + (size_t)14 * 1024;
        float pv[4]; float ss = 0.f;
        #pragma unroll
        for (int i = 0; i < 4; i++) { pv[i] = g_acc_pli[tid + i * 256]; ss += pv[i] * pv[i]; }
        ss = bsum(ss, sred);
        float r = rsqrtf(ss / 1024.f + 1e-6f);
        float sc = lscal[14];
        #pragma unroll
        for (int i = 0; i < 4; i++) {
            int idx = tid + i * 256;
            out[idx] = (g_h2[idx] + pv[i] * r * (1.f + w[idx])) * sc;
        }
    }
    if (do_copy) {
        const float4* kv4 = (const float4*)kv;
        float4* out4 = (float4*)(out + 1024);
        for (int i = gtid; i < 786432; i += NT) {
            float4 v;
            if (i < 131072) {
                int j = i >> 6, d4 = i & 63;
                v = (j == pos) ? ((const float4*)g_k13)[d4]
                               : kv4[((size_t)13 * 2048 + j) * 128 + d4];
            } else if (i < 262144) {
                int t = i - 131072; int j = t >> 6, d4 = t & 63;
                v = (j == pos) ? ((const float4*)g_v13)[d4]
                               : kv4[((size_t)28 * 2048 + j) * 128 + d4];
            } else if (i < 524288) {
                int t = i - 262144; int j = t >> 7, d4 = t & 127;
                v = (j == pos) ? ((const float4*)g_k14)[d4]
                               : kv4[((size_t)14 * 2048 + j) * 128 + d4];
            } else {
                int t = i - 524288; int j = t >> 7, d4 = t & 127;
                v = (j == pos) ? ((const float4*)g_v14)[d4]
                               : kv4[((size_t)29 * 2048 + j) * 128 + d4];
            }
            out4[i] = v;
        }
    }
}

// ---------------- host ----------------
extern "C" void kernel_launch(void* const* d_in, const int* in_sizes, int n_in,
                              void* d_out, int out_size) {
    const float* embed     = (const float*)d_in[0];
    const float* cos_s     = (const float*)d_in[1];
    const float* sin_s     = (const float*)d_in[2];
    const float* cos_f     = (const float*)d_in[3];
    const float* sin_f     = (const float*)d_in[4];
    const float* ln_in     = (const float*)d_in[5];
    const float* ln_pa     = (const float*)d_in[6];
    const float* ln_pff    = (const float*)d_in[7];
    const float* ln_postff = (const float*)d_in[8];
    const float* ln_ppli   = (const float*)d_in[9];
    const float* qn_w      = (const float*)d_in[10];
    const float* kn_w      = (const float*)d_in[11];
    const float* Wq        = (const float*)d_in[12];
    const float* Wk        = (const float*)d_in[13];
    const float* Wv        = (const float*)d_in[14];
    const float* Wo        = (const float*)d_in[15];
    const float* Wg        = (const float*)d_in[16];
    const float* Wu        = (const float*)d_in[17];
    const float* Wd        = (const float*)d_in[18];
    const float* Wpg       = (const float*)d_in[19];
    const float* Wpp       = (const float*)d_in[20];
    const float* lscal     = (const float*)d_in[21];
    const float* kv        = (const float*)d_in[22];
    const float* plc       = (const float*)d_in[23];
    const float* img       = (const float*)d_in[24];
    const int*   ids       = (const int*)d_in[27];
    const int*   pid       = (const int*)d_in[28];
    float* out = (float*)d_out;

    int do_copy = (out_size >= 3146752) ? 1 : 0;
    mega<<<NB, 256>>>(embed, cos_s, sin_s, cos_f, sin_f,
                      ln_in, ln_pa, ln_pff, ln_postff, ln_ppli,
                      qn_w, kn_w, Wq, Wk, Wv, Wo, Wg, Wu, Wd, Wpg, Wpp,
                      lscal, kv, plc, img, ids, pid, out, do_copy);
}